// round 8
// baseline (speedup 1.0000x reference)
#include <cuda_runtime.h>
#include <cuda_fp16.h>
#include <cstdint>

// ---------------------------------------------------------------------------
// PMWA_24842090840472: 3-hop gated graph aggregation
// R8: force occupancy via __launch_bounds__(256,6) (42 regs, 48-warp ceiling),
//     predicate-free main edge loop + peeled tail. fp16 gather, f32x2 accum,
//     bucket CSR.
// ---------------------------------------------------------------------------

#define DIMS 128
#define NMAX 65537
#define CAP 64

__device__ int g_count[NMAX];
__device__ int g_bkt[(size_t)NMAX * CAP];
// fp16 mirrors of h, ping-pong; row = 32 uint2 = 128 halves (dims in order)
__device__ uint2 g_h16[2][(size_t)NMAX * 32];

// ---------------- Threefry-2x32 (JAX key schedule) -------------------------
#define TF_ROUND(x0, x1, r) \
    do { x0 += x1; x1 = ((x1) << (r)) | ((x1) >> (32 - (r))); x1 ^= x0; } while (0)

__host__ __device__ inline void tf2x32(uint32_t k0, uint32_t k1,
                                       uint32_t x0, uint32_t x1,
                                       uint32_t& o0, uint32_t& o1) {
    uint32_t ks0 = k0, ks1 = k1, ks2 = 0x1BD11BDAu ^ k0 ^ k1;
    x0 += ks0; x1 += ks1;
    TF_ROUND(x0, x1, 13); TF_ROUND(x0, x1, 15); TF_ROUND(x0, x1, 26); TF_ROUND(x0, x1, 6);
    x0 += ks1; x1 += ks2 + 1u;
    TF_ROUND(x0, x1, 17); TF_ROUND(x0, x1, 29); TF_ROUND(x0, x1, 16); TF_ROUND(x0, x1, 24);
    x0 += ks2; x1 += ks0 + 2u;
    TF_ROUND(x0, x1, 13); TF_ROUND(x0, x1, 15); TF_ROUND(x0, x1, 26); TF_ROUND(x0, x1, 6);
    x0 += ks0; x1 += ks1 + 3u;
    TF_ROUND(x0, x1, 17); TF_ROUND(x0, x1, 29); TF_ROUND(x0, x1, 16); TF_ROUND(x0, x1, 24);
    x0 += ks1; x1 += ks2 + 4u;
    TF_ROUND(x0, x1, 13); TF_ROUND(x0, x1, 15); TF_ROUND(x0, x1, 26); TF_ROUND(x0, x1, 6);
    x0 += ks2; x1 += ks0 + 5u;
    o0 = x0; o1 = x1;
}

// XLA/Giles float32 erfinv polynomial
__device__ inline float erfinv_xla(float x) {
    float w = -__logf(fmaf(-x, x, 1.0f));
    float p;
    if (w < 5.0f) {
        w -= 2.5f;
        p = 2.81022636e-08f;
        p = fmaf(p, w, 3.43273939e-07f);
        p = fmaf(p, w, -3.5233877e-06f);
        p = fmaf(p, w, -4.39150654e-06f);
        p = fmaf(p, w, 0.00021858087f);
        p = fmaf(p, w, -0.00125372503f);
        p = fmaf(p, w, -0.00417768164f);
        p = fmaf(p, w, 0.246640727f);
        p = fmaf(p, w, 1.50140941f);
    } else {
        w = sqrtf(w) - 3.0f;
        p = -0.000200214257f;
        p = fmaf(p, w, 0.000100950558f);
        p = fmaf(p, w, 0.00134934322f);
        p = fmaf(p, w, -0.00367342844f);
        p = fmaf(p, w, 0.00573950773f);
        p = fmaf(p, w, -0.0076224613f);
        p = fmaf(p, w, 0.00943887047f);
        p = fmaf(p, w, 1.00167406f);
        p = fmaf(p, w, 2.83297682f);
    }
    return p * x;
}

__device__ inline float tf_normal(uint32_t k0, uint32_t k1, uint32_t idx) {
    uint32_t o0, o1;
    tf2x32(k0, k1, 0u, idx, o0, o1);
    uint32_t bits = o0 ^ o1;
    float f = __uint_as_float(0x3f800000u | (bits >> 9)) - 1.0f;
    float u = fmaf(f, 2.0f, -0.99999994f);
    return 1.41421354f * erfinv_xla(u);
}

// ---------------- bucket CSR: zero + single-pass fill ----------------------
__global__ void k_zero(int N) {
    int i = blockIdx.x * blockDim.x + threadIdx.x;
    if (i < N) g_count[i] = 0;
}

__global__ void k_fillb(const int* __restrict__ src, const int* __restrict__ dst, int E) {
    int i = (blockIdx.x * blockDim.x + threadIdx.x) * 2;
    if (i + 1 < E) {
        int2 d = *(const int2*)(dst + i);
        int2 s = *(const int2*)(src + i);
        int p0 = atomicAdd(&g_count[d.x], 1);
        if (p0 < CAP) g_bkt[(size_t)d.x * CAP + p0] = s.x;
        int p1 = atomicAdd(&g_count[d.y], 1);
        if (p1 < CAP) g_bkt[(size_t)d.y * CAP + p1] = s.y;
    } else if (i < E) {
        int d = dst[i];
        int p = atomicAdd(&g_count[d], 1);
        if (p < CAP) g_bkt[(size_t)d * CAP + p] = src[i];
    }
}

// ---------------- helpers --------------------------------------------------
#define BFLY32(d)                                       \
    d += __shfl_xor_sync(0xffffffffu, d, 16);           \
    d += __shfl_xor_sync(0xffffffffu, d, 8);            \
    d += __shfl_xor_sync(0xffffffffu, d, 4);            \
    d += __shfl_xor_sync(0xffffffffu, d, 2);            \
    d += __shfl_xor_sync(0xffffffffu, d, 1);

__device__ __forceinline__ float sigm(float d) {
    return 1.0f / (1.0f + __expf(-d));
}

__device__ __forceinline__ uint2 f4_to_h4(float4 a) {
    __half2 p0 = __floats2half2_rn(a.x, a.y);
    __half2 p1 = __floats2half2_rn(a.z, a.w);
    uint2 u;
    u.x = *(uint32_t*)&p0;
    u.y = *(uint32_t*)&p1;
    return u;
}

#define H2(u) (*(__half2*)&(u))

__device__ __forceinline__ unsigned long long h2_to_f2ull(uint32_t u) {
    float2 f = __half22float2(H2(u));
    unsigned long long r;
    asm("mov.b64 %0, {%1, %2};" : "=l"(r) : "f"(f.x), "f"(f.y));
    return r;
}

// acc += a2 * v (packed f32x2)
#define FMAX2(acc, a2, v) \
    asm("fma.rn.f32x2 %0, %1, %2, %0;" : "+l"(acc) : "l"(a2), "l"(v))

#define ADDX2(acc, v) \
    asm("add.rn.f32x2 %0, %0, %1;" : "+l"(acc) : "l"(v))

// ---------------- normalize x -> out[0] + fp16 mirror ----------------------
__global__ void k_norm(const float* __restrict__ src, float* __restrict__ dst,
                       int N, int sel) {
    int warp = (blockIdx.x * blockDim.x + threadIdx.x) >> 5;
    int lane = threadIdx.x & 31;
    if (warp >= N) return;
    const float4* sv = (const float4*)src;
    float4 a = sv[(size_t)warp * 32 + lane];
    float ss = fmaf(a.x, a.x, fmaf(a.y, a.y, fmaf(a.z, a.z, a.w * a.w)));
    BFLY32(ss);
    float inv = 1.0f / fmaxf(sqrtf(ss), 1e-12f);
    a.x *= inv; a.y *= inv; a.z *= inv; a.w *= inv;
    ((float4*)dst)[(size_t)warp * 32 + lane] = a;
    g_h16[sel][(size_t)warp * 32 + lane] = f4_to_h4(a);
}

// process one group of 4 edges (lanes split in 4 segments of 8)
#define EDGE4_BODY(JEXPR, PRED)                                               \
    {                                                                          \
        int j = (JEXPR);                                                       \
        uint4 vA = __ldg(&hv[(size_t)j * 16 + sl * 2 + 0]);                    \
        uint4 vB = __ldg(&hv[(size_t)j * 16 + sl * 2 + 1]);                    \
        __half2 p = __hmul2(H2(vA.x), H2(hA.x));                               \
        p = __hfma2(H2(vA.y), H2(hA.y), p);                                    \
        p = __hfma2(H2(vA.z), H2(hA.z), p);                                    \
        p = __hfma2(H2(vA.w), H2(hA.w), p);                                    \
        p = __hfma2(H2(vB.x), H2(hB.x), p);                                    \
        p = __hfma2(H2(vB.y), H2(hB.y), p);                                    \
        p = __hfma2(H2(vB.z), H2(hB.z), p);                                    \
        p = __hfma2(H2(vB.w), H2(hB.w), p);                                    \
        float2 pf = __half22float2(p);                                         \
        float d = pf.x + pf.y;                                                 \
        d += __shfl_xor_sync(0xffffffffu, d, 4);                               \
        d += __shfl_xor_sync(0xffffffffu, d, 2);                               \
        d += __shfl_xor_sync(0xffffffffu, d, 1);                               \
        float a = (PRED) ? sigm(d) : 0.f;                                      \
        unsigned long long a2;                                                 \
        asm("mov.b64 %0, {%1, %1};" : "=l"(a2) : "f"(a));                      \
        FMAX2(acc[0], a2, h2_to_f2ull(vA.x));                                  \
        FMAX2(acc[1], a2, h2_to_f2ull(vA.y));                                  \
        FMAX2(acc[2], a2, h2_to_f2ull(vA.z));                                  \
        FMAX2(acc[3], a2, h2_to_f2ull(vA.w));                                  \
        FMAX2(acc[4], a2, h2_to_f2ull(vB.x));                                  \
        FMAX2(acc[5], a2, h2_to_f2ull(vB.y));                                  \
        FMAX2(acc[6], a2, h2_to_f2ull(vB.z));                                  \
        FMAX2(acc[7], a2, h2_to_f2ull(vB.w));                                  \
    }

// ---- fused hop: segment-8 gather/gate + noise + normalize ------------------
__global__ void __launch_bounds__(256, 6) k_hop(float* __restrict__ out, int N,
                                                int selin, int selout,
                                                uint32_t nk0, uint32_t nk1) {
    __shared__ float xch[8][128];
    int wslot = threadIdx.x >> 5;
    int node = (blockIdx.x * blockDim.x + threadIdx.x) >> 5;
    int lane = threadIdx.x & 31;
    if (node >= N) return;
    int seg = lane >> 3;       // which of 4 concurrent edges
    int sl = lane & 7;         // owns dims sl*16 .. sl*16+15  (2 uint4)
    const uint4* __restrict__ hv = (const uint4*)g_h16[selin];  // 16 uint4/row

    uint4 hA = __ldg(&hv[(size_t)node * 16 + sl * 2 + 0]);
    uint4 hB = __ldg(&hv[(size_t)node * 16 + sl * 2 + 1]);
    unsigned long long acc[8];
    #pragma unroll
    for (int i = 0; i < 8; i++) acc[i] = 0ull;

    int cnt = min(g_count[node], CAP);
    const int* bkt = g_bkt + (size_t)node * CAP;

    int e = 0;
    int full = cnt & ~3;                       // full quads: no predicates
    for (; e < full; e += 4)
        EDGE4_BODY(__ldg(&bkt[e + seg]), true)
    if (e < cnt)                               // one predicated tail quad
        EDGE4_BODY(__ldg(&bkt[min(e + seg, cnt - 1)]), (e + seg) < cnt)

    // cross-segment reduce (xor 8, 16) on packed pairs
    #pragma unroll
    for (int i = 0; i < 8; i++) {
        unsigned long long t = __shfl_xor_sync(0xffffffffu, acc[i], 8);
        ADDX2(acc[i], t);
        t = __shfl_xor_sync(0xffffffffu, acc[i], 16);
        ADDX2(acc[i], t);
    }

    // layout exchange: seg-0 lanes hold full sums for dims sl*16..+15
    if (seg == 0) {
        float2* row = (float2*)xch[wslot];
        #pragma unroll
        for (int i = 0; i < 8; i++) {
            float2 f;
            asm("mov.b64 {%0, %1}, %2;" : "=f"(f.x), "=f"(f.y) : "l"(acc[i]));
            row[sl * 8 + i] = f;
        }
    }
    __syncwarp();
    float4 r = ((float4*)xch[wslot])[lane];

    // + SIGMA*normal, l2-normalize, store f32 out + fp16 mirror
    uint32_t base = (uint32_t)node * 128u + (uint32_t)lane * 4u;
    r.x = fmaf(0.1f, tf_normal(nk0, nk1, base + 0u), r.x);
    r.y = fmaf(0.1f, tf_normal(nk0, nk1, base + 1u), r.y);
    r.z = fmaf(0.1f, tf_normal(nk0, nk1, base + 2u), r.z);
    r.w = fmaf(0.1f, tf_normal(nk0, nk1, base + 3u), r.w);
    float ss = fmaf(r.x, r.x, fmaf(r.y, r.y, fmaf(r.z, r.z, r.w * r.w)));
    BFLY32(ss);
    float inv = 1.0f / fmaxf(sqrtf(ss), 1e-12f);
    r.x *= inv; r.y *= inv; r.z *= inv; r.w *= inv;
    ((float4*)out)[(size_t)node * 32 + lane] = r;
    g_h16[selout][(size_t)node * 32 + lane] = f4_to_h4(r);
}

// ---------------------------------------------------------------------------
extern "C" void kernel_launch(void* const* d_in, const int* in_sizes, int n_in,
                              void* d_out, int out_size) {
    const float* x = (const float*)d_in[0];
    const int* ei = (const int*)d_in[1];      // int32 (JAX x64 disabled)
    int N = in_sizes[0] / DIMS;
    int E = in_sizes[1] / 2;
    float* out = (float*)d_out;
    size_t ND = (size_t)N * DIMS;

    uint32_t hk[3][2];
    for (uint32_t i = 0; i < 3; i++) {
        tf2x32(0u, 1u, 0u, i, hk[i][0], hk[i][1]);
    }

    const int* src = ei;
    const int* dst = ei + E;

    int tEdges2 = ((E + 1) / 2 + 255) / 256;
    int nb = (N + 255) / 256;
    int wNodes = (N + 7) / 8;

    // single-pass bucket CSR
    k_zero<<<nb, 256>>>(N);
    k_fillb<<<tEdges2, 256>>>(src, dst, E);

    // out[0] = normalize(x); mirror[0] = fp16(out[0])
    k_norm<<<wNodes, 256>>>(x, out, N, 0);

    // 3 fused hops, ping-pong mirrors
    for (int k = 0; k < 3; k++) {
        float* nxt = out + (size_t)(k + 1) * ND;
        k_hop<<<wNodes, 256>>>(nxt, N, k & 1, (k + 1) & 1, hk[k][0], hk[k][1]);
    }
}

// round 9
// speedup vs baseline: 1.1815x; 1.1815x over previous
#include <cuda_runtime.h>
#include <cuda_fp16.h>
#include <cstdint>

// ---------------------------------------------------------------------------
// PMWA_24842090840472: 3-hop gated graph aggregation
// R9: R6's segment-16 hop kernel (best measured: 53us/hop, no reg squeeze)
//     + R7's single-pass bucket CSR (15us). No other changes.
// ---------------------------------------------------------------------------

#define DIMS 128
#define NMAX 65537
#define CAP 64

__device__ int g_count[NMAX];
__device__ int g_bkt[(size_t)NMAX * CAP];
// fp16 mirrors of h, ping-pong; row = 32 uint2 = 128 halves (dims in order)
__device__ uint2 g_h16[2][(size_t)NMAX * 32];

// ---------------- Threefry-2x32 (JAX key schedule) -------------------------
#define TF_ROUND(x0, x1, r) \
    do { x0 += x1; x1 = ((x1) << (r)) | ((x1) >> (32 - (r))); x1 ^= x0; } while (0)

__host__ __device__ inline void tf2x32(uint32_t k0, uint32_t k1,
                                       uint32_t x0, uint32_t x1,
                                       uint32_t& o0, uint32_t& o1) {
    uint32_t ks0 = k0, ks1 = k1, ks2 = 0x1BD11BDAu ^ k0 ^ k1;
    x0 += ks0; x1 += ks1;
    TF_ROUND(x0, x1, 13); TF_ROUND(x0, x1, 15); TF_ROUND(x0, x1, 26); TF_ROUND(x0, x1, 6);
    x0 += ks1; x1 += ks2 + 1u;
    TF_ROUND(x0, x1, 17); TF_ROUND(x0, x1, 29); TF_ROUND(x0, x1, 16); TF_ROUND(x0, x1, 24);
    x0 += ks2; x1 += ks0 + 2u;
    TF_ROUND(x0, x1, 13); TF_ROUND(x0, x1, 15); TF_ROUND(x0, x1, 26); TF_ROUND(x0, x1, 6);
    x0 += ks0; x1 += ks1 + 3u;
    TF_ROUND(x0, x1, 17); TF_ROUND(x0, x1, 29); TF_ROUND(x0, x1, 16); TF_ROUND(x0, x1, 24);
    x0 += ks1; x1 += ks2 + 4u;
    TF_ROUND(x0, x1, 13); TF_ROUND(x0, x1, 15); TF_ROUND(x0, x1, 26); TF_ROUND(x0, x1, 6);
    x0 += ks2; x1 += ks0 + 5u;
    o0 = x0; o1 = x1;
}

// XLA/Giles float32 erfinv polynomial
__device__ inline float erfinv_xla(float x) {
    float w = -__logf(fmaf(-x, x, 1.0f));
    float p;
    if (w < 5.0f) {
        w -= 2.5f;
        p = 2.81022636e-08f;
        p = fmaf(p, w, 3.43273939e-07f);
        p = fmaf(p, w, -3.5233877e-06f);
        p = fmaf(p, w, -4.39150654e-06f);
        p = fmaf(p, w, 0.00021858087f);
        p = fmaf(p, w, -0.00125372503f);
        p = fmaf(p, w, -0.00417768164f);
        p = fmaf(p, w, 0.246640727f);
        p = fmaf(p, w, 1.50140941f);
    } else {
        w = sqrtf(w) - 3.0f;
        p = -0.000200214257f;
        p = fmaf(p, w, 0.000100950558f);
        p = fmaf(p, w, 0.00134934322f);
        p = fmaf(p, w, -0.00367342844f);
        p = fmaf(p, w, 0.00573950773f);
        p = fmaf(p, w, -0.0076224613f);
        p = fmaf(p, w, 0.00943887047f);
        p = fmaf(p, w, 1.00167406f);
        p = fmaf(p, w, 2.83297682f);
    }
    return p * x;
}

__device__ inline float tf_normal(uint32_t k0, uint32_t k1, uint32_t idx) {
    uint32_t o0, o1;
    tf2x32(k0, k1, 0u, idx, o0, o1);
    uint32_t bits = o0 ^ o1;
    float f = __uint_as_float(0x3f800000u | (bits >> 9)) - 1.0f;
    float u = fmaf(f, 2.0f, -0.99999994f);
    return 1.41421354f * erfinv_xla(u);
}

// ---------------- bucket CSR: zero + single-pass fill ----------------------
__global__ void k_zero(int N) {
    int i = blockIdx.x * blockDim.x + threadIdx.x;
    if (i < N) g_count[i] = 0;
}

__global__ void k_fillb(const int* __restrict__ src, const int* __restrict__ dst, int E) {
    int i = (blockIdx.x * blockDim.x + threadIdx.x) * 2;
    if (i + 1 < E) {
        int2 d = *(const int2*)(dst + i);
        int2 s = *(const int2*)(src + i);
        int p0 = atomicAdd(&g_count[d.x], 1);
        if (p0 < CAP) g_bkt[(size_t)d.x * CAP + p0] = s.x;
        int p1 = atomicAdd(&g_count[d.y], 1);
        if (p1 < CAP) g_bkt[(size_t)d.y * CAP + p1] = s.y;
    } else if (i < E) {
        int d = dst[i];
        int p = atomicAdd(&g_count[d], 1);
        if (p < CAP) g_bkt[(size_t)d * CAP + p] = src[i];
    }
}

// ---------------- helpers --------------------------------------------------
#define BFLY32(d)                                       \
    d += __shfl_xor_sync(0xffffffffu, d, 16);           \
    d += __shfl_xor_sync(0xffffffffu, d, 8);            \
    d += __shfl_xor_sync(0xffffffffu, d, 4);            \
    d += __shfl_xor_sync(0xffffffffu, d, 2);            \
    d += __shfl_xor_sync(0xffffffffu, d, 1);

#define SEGRED(d)                                       \
    d += __shfl_xor_sync(0xffffffffu, d, 8);            \
    d += __shfl_xor_sync(0xffffffffu, d, 4);            \
    d += __shfl_xor_sync(0xffffffffu, d, 2);            \
    d += __shfl_xor_sync(0xffffffffu, d, 1);

__device__ __forceinline__ float sigm(float d) {
    return 1.0f / (1.0f + __expf(-d));
}

__device__ __forceinline__ uint2 f4_to_h4(float4 a) {
    __half2 p0 = __floats2half2_rn(a.x, a.y);
    __half2 p1 = __floats2half2_rn(a.z, a.w);
    uint2 u;
    u.x = *(uint32_t*)&p0;
    u.y = *(uint32_t*)&p1;
    return u;
}

// partial dot over this lane's 8 dims (uint4 = 4 half2), fp16 products/f32 tail
__device__ __forceinline__ float dot8(uint4 v, __half2 h0, __half2 h1,
                                      __half2 h2, __half2 h3) {
    __half2 p = __hmul2(*(__half2*)&v.x, h0);
    p = __hfma2(*(__half2*)&v.y, h1, p);
    p = __hfma2(*(__half2*)&v.z, h2, p);
    p = __hfma2(*(__half2*)&v.w, h3, p);
    float2 f = __half22float2(p);
    return f.x + f.y;
}

__device__ __forceinline__ void accum8(float* acc, uint4 v, float a) {
    float2 f0 = __half22float2(*(__half2*)&v.x);
    float2 f1 = __half22float2(*(__half2*)&v.y);
    float2 f2 = __half22float2(*(__half2*)&v.z);
    float2 f3 = __half22float2(*(__half2*)&v.w);
    acc[0] = fmaf(a, f0.x, acc[0]);
    acc[1] = fmaf(a, f0.y, acc[1]);
    acc[2] = fmaf(a, f1.x, acc[2]);
    acc[3] = fmaf(a, f1.y, acc[3]);
    acc[4] = fmaf(a, f2.x, acc[4]);
    acc[5] = fmaf(a, f2.y, acc[5]);
    acc[6] = fmaf(a, f3.x, acc[6]);
    acc[7] = fmaf(a, f3.y, acc[7]);
}

// ---------------- normalize x -> out[0] + fp16 mirror ----------------------
__global__ void k_norm(const float* __restrict__ src, float* __restrict__ dst,
                       int N, int sel) {
    int warp = (blockIdx.x * blockDim.x + threadIdx.x) >> 5;
    int lane = threadIdx.x & 31;
    if (warp >= N) return;
    const float4* sv = (const float4*)src;
    float4 a = sv[(size_t)warp * 32 + lane];
    float ss = fmaf(a.x, a.x, fmaf(a.y, a.y, fmaf(a.z, a.z, a.w * a.w)));
    BFLY32(ss);
    float inv = 1.0f / fmaxf(sqrtf(ss), 1e-12f);
    a.x *= inv; a.y *= inv; a.z *= inv; a.w *= inv;
    ((float4*)dst)[(size_t)warp * 32 + lane] = a;
    g_h16[sel][(size_t)warp * 32 + lane] = f4_to_h4(a);
}

// ---- fused hop: segment-16 gather/gate + noise + normalize -----------------
__global__ void __launch_bounds__(256) k_hop(float* __restrict__ out, int N,
                                             int selin, int selout,
                                             uint32_t nk0, uint32_t nk1) {
    __shared__ float xch[8][128];
    int wslot = threadIdx.x >> 5;
    int node = (blockIdx.x * blockDim.x + threadIdx.x) >> 5;
    int lane = threadIdx.x & 31;
    if (node >= N) return;
    int seg = lane >> 4;       // which edge of the pair this lane works on
    int sl = lane & 15;        // lane within segment; owns dims sl*8..sl*8+7
    const uint4* __restrict__ hv = (const uint4*)g_h16[selin];   // 16 uint4/row

    uint4 hdu = __ldg(&hv[(size_t)node * 16 + sl]);
    __half2 h0 = *(__half2*)&hdu.x, h1 = *(__half2*)&hdu.y;
    __half2 h2 = *(__half2*)&hdu.z, h3 = *(__half2*)&hdu.w;
    float acc[8] = {0.f, 0.f, 0.f, 0.f, 0.f, 0.f, 0.f, 0.f};

    int cnt = min(g_count[node], CAP);
    const int* bkt = g_bkt + (size_t)node * CAP;
    int e = 0;

    // 4 edges per iteration (2 segment-pairs in flight)
    for (; e + 4 <= cnt; e += 4) {
        int sA = __ldg(&bkt[e + seg]);
        int sB = __ldg(&bkt[e + 2 + seg]);
        uint4 vA = __ldg(&hv[(size_t)sA * 16 + sl]);
        uint4 vB = __ldg(&hv[(size_t)sB * 16 + sl]);
        float dA = dot8(vA, h0, h1, h2, h3);
        float dB = dot8(vB, h0, h1, h2, h3);
        #pragma unroll
        for (int off = 8; off >= 1; off >>= 1) {
            dA += __shfl_xor_sync(0xffffffffu, dA, off);
            dB += __shfl_xor_sync(0xffffffffu, dB, off);
        }
        accum8(acc, vA, sigm(dA));
        accum8(acc, vB, sigm(dB));
    }
    if (e + 2 <= cnt) {
        int sA = __ldg(&bkt[e + seg]);
        uint4 vA = __ldg(&hv[(size_t)sA * 16 + sl]);
        float dA = dot8(vA, h0, h1, h2, h3);
        SEGRED(dA);
        accum8(acc, vA, sigm(dA));
        e += 2;
    }
    if (e < cnt) {
        int s = __ldg(&bkt[e]);               // both segments same edge
        uint4 v = __ldg(&hv[(size_t)s * 16 + sl]);
        float d = dot8(v, h0, h1, h2, h3);
        SEGRED(d);
        float a = (seg == 0) ? sigm(d) : 0.f; // avoid double count
        accum8(acc, v, a);
    }

    // cross-segment sum
    #pragma unroll
    for (int i = 0; i < 8; i++)
        acc[i] += __shfl_xor_sync(0xffffffffu, acc[i], 16);

    // layout exchange: dims sl*8..+7 -> float4 per lane over 32 lanes
    if (seg == 0) {
        #pragma unroll
        for (int i = 0; i < 8; i++) xch[wslot][sl * 8 + i] = acc[i];
    }
    __syncwarp();
    float4 r = ((float4*)xch[wslot])[lane];

    // + SIGMA*normal, l2-normalize, store f32 out + fp16 mirror
    uint32_t base = (uint32_t)node * 128u + (uint32_t)lane * 4u;
    r.x = fmaf(0.1f, tf_normal(nk0, nk1, base + 0u), r.x);
    r.y = fmaf(0.1f, tf_normal(nk0, nk1, base + 1u), r.y);
    r.z = fmaf(0.1f, tf_normal(nk0, nk1, base + 2u), r.z);
    r.w = fmaf(0.1f, tf_normal(nk0, nk1, base + 3u), r.w);
    float ss = fmaf(r.x, r.x, fmaf(r.y, r.y, fmaf(r.z, r.z, r.w * r.w)));
    BFLY32(ss);
    float inv = 1.0f / fmaxf(sqrtf(ss), 1e-12f);
    r.x *= inv; r.y *= inv; r.z *= inv; r.w *= inv;
    ((float4*)out)[(size_t)node * 32 + lane] = r;
    g_h16[selout][(size_t)node * 32 + lane] = f4_to_h4(r);
}

// ---------------------------------------------------------------------------
extern "C" void kernel_launch(void* const* d_in, const int* in_sizes, int n_in,
                              void* d_out, int out_size) {
    const float* x = (const float*)d_in[0];
    const int* ei = (const int*)d_in[1];      // int32 (JAX x64 disabled)
    int N = in_sizes[0] / DIMS;
    int E = in_sizes[1] / 2;
    float* out = (float*)d_out;
    size_t ND = (size_t)N * DIMS;

    uint32_t hk[3][2];
    for (uint32_t i = 0; i < 3; i++) {
        tf2x32(0u, 1u, 0u, i, hk[i][0], hk[i][1]);
    }

    const int* src = ei;
    const int* dst = ei + E;

    int tEdges2 = ((E + 1) / 2 + 255) / 256;
    int nb = (N + 255) / 256;
    int wNodes = (N + 7) / 8;

    // single-pass bucket CSR
    k_zero<<<nb, 256>>>(N);
    k_fillb<<<tEdges2, 256>>>(src, dst, E);

    // out[0] = normalize(x); mirror[0] = fp16(out[0])
    k_norm<<<wNodes, 256>>>(x, out, N, 0);

    // 3 fused hops, ping-pong mirrors
    for (int k = 0; k < 3; k++) {
        float* nxt = out + (size_t)(k + 1) * ND;
        k_hop<<<wNodes, 256>>>(nxt, N, k & 1, (k + 1) & 1, hk[k][0], hk[k][1]);
    }
}